// round 13
// baseline (speedup 1.0000x reference)
#include <cuda_runtime.h>

#define PI_F 3.14159265358979f

typedef unsigned long long u64;
struct P { u64 v; };

__device__ __forceinline__ P mkP(u64 x){ P r; r.v = x; return r; }
__device__ __forceinline__ P pack2(float lo, float hi){
    P r; asm("mov.b64 %0,{%1,%2};" : "=l"(r.v) : "f"(lo), "f"(hi)); return r;
}
__device__ __forceinline__ P dupP(float v){
    P r; asm("mov.b64 %0,{%1,%1};" : "=l"(r.v) : "f"(v)); return r;
}
__device__ __forceinline__ void unpack2(P a, float& lo, float& hi){
    asm("mov.b64 {%0,%1},%2;" : "=f"(lo), "=f"(hi) : "l"(a.v));
}
__device__ __forceinline__ P fma2(P a, P b, P c){
    P r; asm("fma.rn.f32x2 %0,%1,%2,%3;" : "=l"(r.v) : "l"(a.v), "l"(b.v), "l"(c.v)); return r;
}
#define K_ZERO (mkP(0ULL))
__device__ __forceinline__ P mul2(P a, P b){ return fma2(a, b, K_ZERO); }

// shared layout (floats). MLP weights TRANSPOSED, adjacent-neuron pairs.
#define OFF_W1   0      // 64
#define OFF_B1   64     // 16
#define OFF_W2   80     // 512
#define OFF_B2   592    // 32
#define OFF_W3   624    // 512
#define OFF_B3   1136   // 16
#define OFF_C    1152   // 60 (30 pair-duplicated Heisenberg coefficients)
#define SW_TOTAL 1216

#define BLK 96

// Quantum encoder for one packed batch-pair (lane0=A, lane1=B).
__device__ __forceinline__ void quantum_pair(
    const float* __restrict__ xA, const float* __restrict__ xB,
    const float* __restrict__ sw, P* __restrict__ eo)
{
    P bz[4], bx[4], by[4];
#pragma unroll
    for (int i = 0; i < 4; i++) {
        float sA, cA, sB, cB, pA, qA, pB, qB;
        __sincosf(xA[i] * PI_F, &sA, &cA);
        __sincosf(xB[i] * PI_F, &sB, &cB);
        __sincosf(xA[i+4] * PI_F, &pA, &qA);
        __sincosf(xB[i+4] * PI_F, &pB, &qB);
        bz[i] = pack2(cA, cB);
        P sp = pack2(sA, sB);
        bx[i] = mul2(sp, pack2(qA, qB));
        by[i] = mul2(sp, pack2(pA, pB));
    }
    const P* Kp = (const P*)(sw + OFF_C);

    P a_ = mul2(bx[0], bx[1]);
    P b_ = mul2(bx[1], bx[2]);
    P c_ = mul2(bx[0], bx[2]);
    P d_ = mul2(by[0], by[1]);
    P e_ = mul2(by[1], by[2]);
    P f_ = mul2(bx[2], bx[3]);
    P h_ = mul2(bx[0], bx[3]);
    P i_ = mul2(bz[0], bz[2]);
    P j_ = mul2(by[2], by[3]);
    P k_ = mul2(bz[1], bz[3]);
    P l_ = mul2(bz[0], bx[1]);
    P m_ = mul2(by[0], bz[1]);
    P u_ = mul2(bz[0], b_);
    P v_ = mul2(a_, bz[2]);
    P w_ = mul2(m_, by[2]);

    eo[0] = fma2(Kp[1], a_, mul2(Kp[0], bz[0]));

    P e1 = fma2(Kp[3], u_, mul2(Kp[2], bz[1]));
    e1 = fma2(Kp[4], d_, e1);
    eo[1] = fma2(Kp[5], c_, e1);

    P e2 = mul2(Kp[6], i_);
    e2 = fma2(Kp[7],  mul2(bz[1], f_), e2);
    e2 = fma2(Kp[8],  e_, e2);
    e2 = fma2(Kp[9],  mul2(l_, bx[3]), e2);
    e2 = fma2(Kp[10], v_, e2);
    e2 = fma2(Kp[11], mul2(d_, f_), e2);
    e2 = fma2(Kp[12], w_, e2);
    eo[2] = fma2(Kp[13], h_, e2);

    P e3 = mul2(Kp[14], k_);
    e3 = fma2(Kp[15], mul2(i_, bx[3]), e3);
    e3 = fma2(Kp[16], mul2(bz[0], j_), e3);
    e3 = fma2(Kp[17], mul2(bz[1], bx[2]), e3);
    e3 = fma2(Kp[18], mul2(u_, bz[3]), e3);
    e3 = fma2(Kp[19], mul2(e_, bx[3]), e3);
    e3 = fma2(Kp[20], mul2(mul2(by[1], bz[2]), by[3]), e3);
    e3 = fma2(Kp[21], l_, e3);
    e3 = fma2(Kp[22], mul2(d_, bz[3]), e3);
    e3 = fma2(Kp[23], mul2(v_, bx[3]), e3);
    e3 = fma2(Kp[24], mul2(a_, j_), e3);
    e3 = fma2(Kp[25], mul2(d_, bx[2]), e3);
    e3 = fma2(Kp[26], mul2(c_, bz[3]), e3);
    e3 = fma2(Kp[27], mul2(w_, bx[3]), e3);
    e3 = fma2(Kp[28], mul2(mul2(m_, bz[2]), by[3]), e3);
    eo[3] = fma2(Kp[29], bx[0], e3);
}

__global__ __launch_bounds__(BLK, 3) void hqae_kernel(
    const float* __restrict__ x,  const float* __restrict__ qw,
    const float* __restrict__ W1, const float* __restrict__ b1,
    const float* __restrict__ W2, const float* __restrict__ b2,
    const float* __restrict__ W3, const float* __restrict__ b3,
    float* __restrict__ out, int n)
{
    __shared__ __align__(16) float sw[SW_TOTAL];
    const int tid = threadIdx.x;

    for (int i = tid; i < 64;  i += BLK){ int k = i >> 4, j = i & 15; sw[OFF_W1 + i] = W1[j*4 + k]; }
    for (int i = tid; i < 512; i += BLK){ int k = i >> 5, j = i & 31; sw[OFF_W2 + i] = W2[j*16 + k]; }
    for (int i = tid; i < 512; i += BLK){ int k = i >> 4, j = i & 15; sw[OFF_W3 + i] = W3[j*32 + k]; }
    for (int i = tid; i < 16;  i += BLK) sw[OFF_B1 + i] = b1[i];
    for (int i = tid; i < 32;  i += BLK) sw[OFF_B2 + i] = b2[i];
    for (int i = tid; i < 16;  i += BLK) sw[OFF_B3 + i] = b3[i];
    if (tid == 0) {
        // Heisenberg coefficients (variational RZ drops under |.|^2).
        float c[4], s[4];
#pragma unroll
        for (int i = 0; i < 4; i++) __sincosf(qw[2*i], &s[i], &c[i]);
        float K[30];
        K[0]=+c[0];                 K[1]=-s[0];
        K[2]=+c[0]*c[1];            K[3]=-c[0]*s[1];
        K[4]=+s[0]*c[1];            K[5]=+s[0]*s[1];
        K[6]=+c[0]*c[1]*c[2];       K[7]=-c[0]*c[1]*s[2];
        K[8]=+c[0]*s[1]*c[2];       K[9]=+c[0]*s[1]*s[2];
        K[10]=-s[0]*c[1]*c[2];      K[11]=-s[0]*c[1]*s[2];
        K[12]=-s[0]*s[1]*c[2];      K[13]=-s[0]*s[1]*s[2];
        K[14]=+c[0]*c[1]*c[2]*c[3]; K[15]=-c[0]*c[1]*c[2]*s[3];
        K[16]=+c[0]*c[1]*s[2]*c[3]; K[17]=+c[0]*c[1]*s[2]*s[3];
        K[18]=-c[0]*s[1]*c[2]*c[3]; K[19]=-c[0]*s[1]*c[2]*s[3];
        K[20]=-c[0]*s[1]*s[2]*c[3]; K[21]=-c[0]*s[1]*s[2]*s[3];
        K[22]=+s[0]*c[1]*c[2]*c[3]; K[23]=+s[0]*c[1]*c[2]*s[3];
        K[24]=-s[0]*c[1]*s[2]*c[3]; K[25]=+s[0]*c[1]*s[2]*s[3];
        K[26]=+s[0]*s[1]*c[2]*c[3]; K[27]=+s[0]*s[1]*c[2]*s[3];
        K[28]=+s[0]*s[1]*s[2]*c[3]; K[29]=+s[0]*s[1]*s[2]*s[3];
#pragma unroll
        for (int i = 0; i < 30; i++){ sw[OFF_C + 2*i] = K[i]; sw[OFF_C + 2*i + 1] = K[i]; }
    }
    __syncthreads();

    const int quart = n >> 2;                 // elements b0, +q, +2q, +3q
    const int b0 = blockIdx.x * BLK + tid;
    if (b0 >= quart) return;

    // ---- load x rows for 4 elements ----
    float xr[4][8];
#pragma unroll
    for (int e = 0; e < 4; e++) {
        const float4* xv = (const float4*)(x + (size_t)(b0 + e*quart) * 16);
        float4 v0 = xv[0], v1 = xv[1];
        xr[e][0]=v0.x; xr[e][1]=v0.y; xr[e][2]=v0.z; xr[e][3]=v0.w;
        xr[e][4]=v1.x; xr[e][5]=v1.y; xr[e][6]=v1.z; xr[e][7]=v1.w;
    }

    // ---- quantum encoder: two packed pairs (0,1) and (2,3) ----
    float z[4][4];
    {
        P ep[4];
        quantum_pair(xr[0], xr[1], sw, ep);
#pragma unroll
        for (int i = 0; i < 4; i++) unpack2(ep[i], z[0][i], z[1][i]);
        quantum_pair(xr[2], xr[3], sw, ep);
#pragma unroll
        for (int i = 0; i < 4; i++) unpack2(ep[i], z[2][i], z[3][i]);
    }

    // ================= MLP: neuron-pair packing, weights shared by 4 elements ==========
    const P* B1p = (const P*)(sw + OFF_B1);
    const P* B2p = (const P*)(sw + OFF_B2);
    const P* B3p = (const P*)(sw + OFF_B3);

    // ---- layer 1: 4 -> 16 ----
    float h1[4][16];
    {
        P acc[4][8];
#pragma unroll
        for (int jp = 0; jp < 8; jp++) {
            P bb = B1p[jp];
#pragma unroll
            for (int e = 0; e < 4; e++) acc[e][jp] = bb;
        }
#pragma unroll
        for (int k = 0; k < 4; k++) {
            P d[4];
#pragma unroll
            for (int e = 0; e < 4; e++) d[e] = dupP(z[e][k]);
            const ulonglong2* row = (const ulonglong2*)(sw + OFF_W1 + k*16);
#pragma unroll
            for (int q = 0; q < 4; q++) {
                ulonglong2 u = row[q];
                P w0 = mkP(u.x), w1 = mkP(u.y);
#pragma unroll
                for (int e = 0; e < 4; e++) {
                    acc[e][2*q]   = fma2(w0, d[e], acc[e][2*q]);
                    acc[e][2*q+1] = fma2(w1, d[e], acc[e][2*q+1]);
                }
            }
        }
#pragma unroll
        for (int e = 0; e < 4; e++)
#pragma unroll
            for (int jp = 0; jp < 8; jp++) {
                float lo, hi;
                unpack2(acc[e][jp], lo, hi);
                h1[e][2*jp] = fmaxf(lo, 0.0f); h1[e][2*jp+1] = fmaxf(hi, 0.0f);
            }
    }

    // ---- layer 2: 16 -> 32, 2 chunks of 16 neurons ----
    float h2[4][32];
#pragma unroll
    for (int c = 0; c < 2; c++) {
        P acc[4][8];
#pragma unroll
        for (int jp = 0; jp < 8; jp++) {
            P bb = B2p[c*8 + jp];
#pragma unroll
            for (int e = 0; e < 4; e++) acc[e][jp] = bb;
        }
#pragma unroll
        for (int k = 0; k < 16; k++) {
            P d[4];
#pragma unroll
            for (int e = 0; e < 4; e++) d[e] = dupP(h1[e][k]);
            const ulonglong2* row = (const ulonglong2*)(sw + OFF_W2 + k*32 + c*16);
#pragma unroll
            for (int q = 0; q < 4; q++) {
                ulonglong2 u = row[q];
                P w0 = mkP(u.x), w1 = mkP(u.y);
#pragma unroll
                for (int e = 0; e < 4; e++) {
                    acc[e][2*q]   = fma2(w0, d[e], acc[e][2*q]);
                    acc[e][2*q+1] = fma2(w1, d[e], acc[e][2*q+1]);
                }
            }
        }
#pragma unroll
        for (int e = 0; e < 4; e++)
#pragma unroll
            for (int jp = 0; jp < 8; jp++) {
                float lo, hi;
                unpack2(acc[e][jp], lo, hi);
                h2[e][c*16 + 2*jp] = fmaxf(lo, 0.0f); h2[e][c*16 + 2*jp+1] = fmaxf(hi, 0.0f);
            }
    }

    // ---- layer 3: 32 -> 16, full width, all 4 elements ----
    {
        P acc[4][8];
#pragma unroll
        for (int jp = 0; jp < 8; jp++) {
            P bb = B3p[jp];
#pragma unroll
            for (int e = 0; e < 4; e++) acc[e][jp] = bb;
        }
#pragma unroll
        for (int k = 0; k < 32; k++) {
            P d[4];
#pragma unroll
            for (int e = 0; e < 4; e++) d[e] = dupP(h2[e][k]);
            const ulonglong2* row = (const ulonglong2*)(sw + OFF_W3 + k*16);
#pragma unroll
            for (int q = 0; q < 4; q++) {
                ulonglong2 u = row[q];
                P w0 = mkP(u.x), w1 = mkP(u.y);
#pragma unroll
                for (int e = 0; e < 4; e++) {
                    acc[e][2*q]   = fma2(w0, d[e], acc[e][2*q]);
                    acc[e][2*q+1] = fma2(w1, d[e], acc[e][2*q+1]);
                }
            }
        }
#pragma unroll
        for (int e = 0; e < 4; e++) {
            float* o = out + (size_t)(b0 + e*quart) * 16;
#pragma unroll
            for (int g = 0; g < 4; g++) {
                float4 v;
                unpack2(acc[e][2*g],   v.x, v.y);
                unpack2(acc[e][2*g+1], v.z, v.w);
                ((float4*)o)[g] = v;
            }
        }
    }
}

extern "C" void kernel_launch(void* const* d_in, const int* in_sizes, int n_in,
                              void* d_out, int out_size)
{
    const float* x  = (const float*)d_in[0];
    const float* qw = (const float*)d_in[1];
    const float* W1 = (const float*)d_in[2];
    const float* b1 = (const float*)d_in[3];
    const float* W2 = (const float*)d_in[4];
    const float* b2 = (const float*)d_in[5];
    const float* W3 = (const float*)d_in[6];
    const float* b3 = (const float*)d_in[7];
    float* out = (float*)d_out;

    const int n = in_sizes[0] / 16;           // B (divisible by 4)
    const int quart = n >> 2;
    const int blocks = (quart + BLK - 1) / BLK;
    hqae_kernel<<<blocks, BLK>>>(x, qw, W1, b1, W2, b2, W3, b3, out, n);
}

// round 14
// speedup vs baseline: 1.1405x; 1.1405x over previous
#include <cuda_runtime.h>

#define PI_F 3.14159265358979f

typedef unsigned long long u64;
struct P { u64 v; };

__device__ __forceinline__ P mkP(u64 x){ P r; r.v = x; return r; }
__device__ __forceinline__ P pack2(float lo, float hi){
    P r; asm("mov.b64 %0,{%1,%2};" : "=l"(r.v) : "f"(lo), "f"(hi)); return r;
}
__device__ __forceinline__ P dupP(float v){
    P r; asm("mov.b64 %0,{%1,%1};" : "=l"(r.v) : "f"(v)); return r;
}
__device__ __forceinline__ void unpack2(P a, float& lo, float& hi){
    asm("mov.b64 {%0,%1},%2;" : "=f"(lo), "=f"(hi) : "l"(a.v));
}
__device__ __forceinline__ P fma2(P a, P b, P c){
    P r; asm("fma.rn.f32x2 %0,%1,%2,%3;" : "=l"(r.v) : "l"(a.v), "l"(b.v), "l"(c.v)); return r;
}
#define K_ZERO (mkP(0ULL))
__device__ __forceinline__ P mul2(P a, P b){ return fma2(a, b, K_ZERO); }

// shared layout (floats). MLP weights TRANSPOSED, adjacent-neuron pairs.
#define OFF_W1   0      // 64
#define OFF_B1   64     // 16
#define OFF_W2   80     // 512
#define OFF_B2   592    // 32
#define OFF_W3   624    // 512
#define OFF_B3   1136   // 16
#define OFF_C    1152   // 60 (30 pair-duplicated Heisenberg coefficients)
#define SW_TOTAL 1216

#define BLK 128

// 30-term Pauli-string evaluation for one packed pair given Bloch vectors.
__device__ __forceinline__ void pauli_eval(
    const P* __restrict__ bz, const P* __restrict__ bx, const P* __restrict__ by,
    const P* __restrict__ Kp, P* __restrict__ eo)
{
    P a_ = mul2(bx[0], bx[1]);
    P b_ = mul2(bx[1], bx[2]);
    P c_ = mul2(bx[0], bx[2]);
    P d_ = mul2(by[0], by[1]);
    P e_ = mul2(by[1], by[2]);
    P f_ = mul2(bx[2], bx[3]);
    P h_ = mul2(bx[0], bx[3]);
    P i_ = mul2(bz[0], bz[2]);
    P j_ = mul2(by[2], by[3]);
    P k_ = mul2(bz[1], bz[3]);
    P l_ = mul2(bz[0], bx[1]);
    P m_ = mul2(by[0], bz[1]);
    P u_ = mul2(bz[0], b_);
    P v_ = mul2(a_, bz[2]);
    P w_ = mul2(m_, by[2]);

    eo[0] = fma2(Kp[1], a_, mul2(Kp[0], bz[0]));

    P e1 = fma2(Kp[3], u_, mul2(Kp[2], bz[1]));
    e1 = fma2(Kp[4], d_, e1);
    eo[1] = fma2(Kp[5], c_, e1);

    P e2 = mul2(Kp[6], i_);
    e2 = fma2(Kp[7],  mul2(bz[1], f_), e2);
    e2 = fma2(Kp[8],  e_, e2);
    e2 = fma2(Kp[9],  mul2(l_, bx[3]), e2);
    e2 = fma2(Kp[10], v_, e2);
    e2 = fma2(Kp[11], mul2(d_, f_), e2);
    e2 = fma2(Kp[12], w_, e2);
    eo[2] = fma2(Kp[13], h_, e2);

    P e3 = mul2(Kp[14], k_);
    e3 = fma2(Kp[15], mul2(i_, bx[3]), e3);
    e3 = fma2(Kp[16], mul2(bz[0], j_), e3);
    e3 = fma2(Kp[17], mul2(bz[1], bx[2]), e3);
    e3 = fma2(Kp[18], mul2(u_, bz[3]), e3);
    e3 = fma2(Kp[19], mul2(e_, bx[3]), e3);
    e3 = fma2(Kp[20], mul2(mul2(by[1], bz[2]), by[3]), e3);
    e3 = fma2(Kp[21], l_, e3);
    e3 = fma2(Kp[22], mul2(d_, bz[3]), e3);
    e3 = fma2(Kp[23], mul2(v_, bx[3]), e3);
    e3 = fma2(Kp[24], mul2(a_, j_), e3);
    e3 = fma2(Kp[25], mul2(d_, bx[2]), e3);
    e3 = fma2(Kp[26], mul2(c_, bz[3]), e3);
    e3 = fma2(Kp[27], mul2(w_, bx[3]), e3);
    e3 = fma2(Kp[28], mul2(mul2(m_, bz[2]), by[3]), e3);
    eo[3] = fma2(Kp[29], bx[0], e3);
}

__global__ __launch_bounds__(BLK, 2) void hqae_kernel(
    const float* __restrict__ x,  const float* __restrict__ qw,
    const float* __restrict__ W1, const float* __restrict__ b1,
    const float* __restrict__ W2, const float* __restrict__ b2,
    const float* __restrict__ W3, const float* __restrict__ b3,
    float* __restrict__ out, int n)
{
    __shared__ __align__(16) float sw[SW_TOTAL];
    const int tid = threadIdx.x;

    for (int i = tid; i < 64;  i += BLK){ int k = i >> 4, j = i & 15; sw[OFF_W1 + i] = W1[j*4 + k]; }
    for (int i = tid; i < 512; i += BLK){ int k = i >> 5, j = i & 31; sw[OFF_W2 + i] = W2[j*16 + k]; }
    for (int i = tid; i < 512; i += BLK){ int k = i >> 4, j = i & 15; sw[OFF_W3 + i] = W3[j*32 + k]; }
    for (int i = tid; i < 16;  i += BLK) sw[OFF_B1 + i] = b1[i];
    for (int i = tid; i < 32;  i += BLK) sw[OFF_B2 + i] = b2[i];
    for (int i = tid; i < 16;  i += BLK) sw[OFF_B3 + i] = b3[i];
    if (tid == 0) {
        // Heisenberg coefficients (variational RZ drops under |.|^2).
        float c[4], s[4];
#pragma unroll
        for (int i = 0; i < 4; i++) __sincosf(qw[2*i], &s[i], &c[i]);
        float K[30];
        K[0]=+c[0];                 K[1]=-s[0];
        K[2]=+c[0]*c[1];            K[3]=-c[0]*s[1];
        K[4]=+s[0]*c[1];            K[5]=+s[0]*s[1];
        K[6]=+c[0]*c[1]*c[2];       K[7]=-c[0]*c[1]*s[2];
        K[8]=+c[0]*s[1]*c[2];       K[9]=+c[0]*s[1]*s[2];
        K[10]=-s[0]*c[1]*c[2];      K[11]=-s[0]*c[1]*s[2];
        K[12]=-s[0]*s[1]*c[2];      K[13]=-s[0]*s[1]*s[2];
        K[14]=+c[0]*c[1]*c[2]*c[3]; K[15]=-c[0]*c[1]*c[2]*s[3];
        K[16]=+c[0]*c[1]*s[2]*c[3]; K[17]=+c[0]*c[1]*s[2]*s[3];
        K[18]=-c[0]*s[1]*c[2]*c[3]; K[19]=-c[0]*s[1]*c[2]*s[3];
        K[20]=-c[0]*s[1]*s[2]*c[3]; K[21]=-c[0]*s[1]*s[2]*s[3];
        K[22]=+s[0]*c[1]*c[2]*c[3]; K[23]=+s[0]*c[1]*c[2]*s[3];
        K[24]=-s[0]*c[1]*s[2]*c[3]; K[25]=+s[0]*c[1]*s[2]*s[3];
        K[26]=+s[0]*s[1]*c[2]*c[3]; K[27]=+s[0]*s[1]*c[2]*s[3];
        K[28]=+s[0]*s[1]*s[2]*c[3]; K[29]=+s[0]*s[1]*s[2]*s[3];
#pragma unroll
        for (int i = 0; i < 30; i++){ sw[OFF_C + 2*i] = K[i]; sw[OFF_C + 2*i + 1] = K[i]; }
    }
    __syncthreads();

    const int quart = n >> 2;                 // elements b0, +q, +2q, +3q
    const int b0 = blockIdx.x * BLK + tid;
    if (b0 >= quart) return;

    // ---- load x rows for 4 elements ----
    float xr[4][8];
#pragma unroll
    for (int e = 0; e < 4; e++) {
        const float4* xv = (const float4*)(x + (size_t)(b0 + e*quart) * 16);
        float4 v0 = xv[0], v1 = xv[1];
        xr[e][0]=v0.x; xr[e][1]=v0.y; xr[e][2]=v0.z; xr[e][3]=v0.w;
        xr[e][4]=v1.x; xr[e][5]=v1.y; xr[e][6]=v1.z; xr[e][7]=v1.w;
    }

    // ---- quantum encoder: BOTH pairs' sincos batched first (64 indep MUFU),
    //      then both monomial trees (interleavable by the scheduler) ----
    float z[4][4];
    {
        P bz[2][4], bx[2][4], by[2][4];
#pragma unroll
        for (int p = 0; p < 2; p++) {
            const float* xA = xr[2*p];
            const float* xB = xr[2*p + 1];
#pragma unroll
            for (int i = 0; i < 4; i++) {
                float sA, cA, sB, cB, pA, qA, pB, qB;
                __sincosf(xA[i] * PI_F, &sA, &cA);
                __sincosf(xB[i] * PI_F, &sB, &cB);
                __sincosf(xA[i+4] * PI_F, &pA, &qA);
                __sincosf(xB[i+4] * PI_F, &pB, &qB);
                bz[p][i] = pack2(cA, cB);
                P sp = pack2(sA, sB);
                bx[p][i] = mul2(sp, pack2(qA, qB));
                by[p][i] = mul2(sp, pack2(pA, pB));
            }
        }
        const P* Kp = (const P*)(sw + OFF_C);
        P ep0[4], ep1[4];
        pauli_eval(bz[0], bx[0], by[0], Kp, ep0);
        pauli_eval(bz[1], bx[1], by[1], Kp, ep1);
#pragma unroll
        for (int i = 0; i < 4; i++) {
            unpack2(ep0[i], z[0][i], z[1][i]);
            unpack2(ep1[i], z[2][i], z[3][i]);
        }
    }

    // ================= MLP: neuron-pair packing, weights shared by 4 elements ==========
    const P* B1p = (const P*)(sw + OFF_B1);
    const P* B2p = (const P*)(sw + OFF_B2);
    const P* B3p = (const P*)(sw + OFF_B3);

    // ---- layer 1: 4 -> 16 ----
    float h1[4][16];
    {
        P acc[4][8];
#pragma unroll
        for (int jp = 0; jp < 8; jp++) {
            P bb = B1p[jp];
#pragma unroll
            for (int e = 0; e < 4; e++) acc[e][jp] = bb;
        }
#pragma unroll
        for (int k = 0; k < 4; k++) {
            P d[4];
#pragma unroll
            for (int e = 0; e < 4; e++) d[e] = dupP(z[e][k]);
            const ulonglong2* row = (const ulonglong2*)(sw + OFF_W1 + k*16);
#pragma unroll
            for (int q = 0; q < 4; q++) {
                ulonglong2 u = row[q];
                P w0 = mkP(u.x), w1 = mkP(u.y);
#pragma unroll
                for (int e = 0; e < 4; e++) {
                    acc[e][2*q]   = fma2(w0, d[e], acc[e][2*q]);
                    acc[e][2*q+1] = fma2(w1, d[e], acc[e][2*q+1]);
                }
            }
        }
#pragma unroll
        for (int e = 0; e < 4; e++)
#pragma unroll
            for (int jp = 0; jp < 8; jp++) {
                float lo, hi;
                unpack2(acc[e][jp], lo, hi);
                h1[e][2*jp] = fmaxf(lo, 0.0f); h1[e][2*jp+1] = fmaxf(hi, 0.0f);
            }
    }

    // ---- layer 2: 16 -> 32, 2 chunks of 16 neurons ----
    float h2[4][32];
#pragma unroll
    for (int c = 0; c < 2; c++) {
        P acc[4][8];
#pragma unroll
        for (int jp = 0; jp < 8; jp++) {
            P bb = B2p[c*8 + jp];
#pragma unroll
            for (int e = 0; e < 4; e++) acc[e][jp] = bb;
        }
#pragma unroll
        for (int k = 0; k < 16; k++) {
            P d[4];
#pragma unroll
            for (int e = 0; e < 4; e++) d[e] = dupP(h1[e][k]);
            const ulonglong2* row = (const ulonglong2*)(sw + OFF_W2 + k*32 + c*16);
#pragma unroll
            for (int q = 0; q < 4; q++) {
                ulonglong2 u = row[q];
                P w0 = mkP(u.x), w1 = mkP(u.y);
#pragma unroll
                for (int e = 0; e < 4; e++) {
                    acc[e][2*q]   = fma2(w0, d[e], acc[e][2*q]);
                    acc[e][2*q+1] = fma2(w1, d[e], acc[e][2*q+1]);
                }
            }
        }
#pragma unroll
        for (int e = 0; e < 4; e++)
#pragma unroll
            for (int jp = 0; jp < 8; jp++) {
                float lo, hi;
                unpack2(acc[e][jp], lo, hi);
                h2[e][c*16 + 2*jp] = fmaxf(lo, 0.0f); h2[e][c*16 + 2*jp+1] = fmaxf(hi, 0.0f);
            }
    }

    // ---- layer 3: 32 -> 16, full width, all 4 elements ----
    {
        P acc[4][8];
#pragma unroll
        for (int jp = 0; jp < 8; jp++) {
            P bb = B3p[jp];
#pragma unroll
            for (int e = 0; e < 4; e++) acc[e][jp] = bb;
        }
#pragma unroll
        for (int k = 0; k < 32; k++) {
            P d[4];
#pragma unroll
            for (int e = 0; e < 4; e++) d[e] = dupP(h2[e][k]);
            const ulonglong2* row = (const ulonglong2*)(sw + OFF_W3 + k*16);
#pragma unroll
            for (int q = 0; q < 4; q++) {
                ulonglong2 u = row[q];
                P w0 = mkP(u.x), w1 = mkP(u.y);
#pragma unroll
                for (int e = 0; e < 4; e++) {
                    acc[e][2*q]   = fma2(w0, d[e], acc[e][2*q]);
                    acc[e][2*q+1] = fma2(w1, d[e], acc[e][2*q+1]);
                }
            }
        }
#pragma unroll
        for (int e = 0; e < 4; e++) {
            float* o = out + (size_t)(b0 + e*quart) * 16;
#pragma unroll
            for (int g = 0; g < 4; g++) {
                float4 v;
                unpack2(acc[e][2*g],   v.x, v.y);
                unpack2(acc[e][2*g+1], v.z, v.w);
                ((float4*)o)[g] = v;
            }
        }
    }
}

extern "C" void kernel_launch(void* const* d_in, const int* in_sizes, int n_in,
                              void* d_out, int out_size)
{
    const float* x  = (const float*)d_in[0];
    const float* qw = (const float*)d_in[1];
    const float* W1 = (const float*)d_in[2];
    const float* b1 = (const float*)d_in[3];
    const float* W2 = (const float*)d_in[4];
    const float* b2 = (const float*)d_in[5];
    const float* W3 = (const float*)d_in[6];
    const float* b3 = (const float*)d_in[7];
    float* out = (float*)d_out;

    const int n = in_sizes[0] / 16;           // B (divisible by 4)
    const int quart = n >> 2;
    const int blocks = (quart + BLK - 1) / BLK;
    hqae_kernel<<<blocks, BLK>>>(x, qw, W1, b1, W2, b2, W3, b3, out, n);
}

// round 16
// speedup vs baseline: 1.2191x; 1.0689x over previous
#include <cuda_runtime.h>
#include <cuda_bf16.h>
#include <cstdint>

#define PI_F 3.14159265358979f

// ---------------- generic-PTX tensor helpers (sm_80+, legal on compute_103) --------
__device__ __forceinline__ uint32_t smem_u32(const void* p){
    uint32_t a;
    asm("{ .reg .u64 t; cvta.to.shared.u64 t, %1; cvt.u32.u64 %0, t; }" : "=r"(a) : "l"(p));
    return a;
}
__device__ __forceinline__ void ldm4(uint32_t* d, uint32_t a){
    asm volatile("ldmatrix.sync.aligned.m8n8.x4.shared.b16 {%0,%1,%2,%3}, [%4];"
        : "=r"(d[0]), "=r"(d[1]), "=r"(d[2]), "=r"(d[3]) : "r"(a));
}
__device__ __forceinline__ void mma16816(float& c0, float& c1, float& c2, float& c3,
                                         const uint32_t* a, uint32_t b0, uint32_t b1){
    asm volatile("mma.sync.aligned.m16n8k16.row.col.f32.bf16.bf16.f32 "
        "{%0,%1,%2,%3},{%4,%5,%6,%7},{%8,%9},{%0,%1,%2,%3};"
        : "+f"(c0), "+f"(c1), "+f"(c2), "+f"(c3)
        : "r"(a[0]), "r"(a[1]), "r"(a[2]), "r"(a[3]), "r"(b0), "r"(b1));
}
__device__ __forceinline__ void bsplit(float v, float& hi, float& lo){
    __nv_bfloat16 h = __float2bfloat16(v);
    hi = __bfloat162float(h);
    lo = v - hi;
}
__device__ __forceinline__ uint32_t bpack(float a, float b){
    __nv_bfloat162 t = __floats2bfloat162_rn(a, b);   // .x = a (low), .y = b (high)
    return *reinterpret_cast<uint32_t*>(&t);
}

// ---------------- smem layout (bytes) ----------------
#define SM_W1   0       // 16x4 f32 = 256
#define SM_SB1  256     // 16 f32
#define SM_SB2  320     // 32 f32
#define SM_SB3  448     // 16 f32
#define SM_KC   512     // 30 f32 (pad 128)
#define SM_W2H  640     // [32][16] bf16 = 1024, row stride 32B
#define SM_W2L  1664
#define SM_W3H  2688    // [16][32] bf16 = 1024, row stride 64B
#define SM_W3L  3712
#define SM_HST  4736    // per warp: hi 32 rows x 80B = 2560, lo 2560 -> 5120/warp
#define WARP_STG 5120
#define SM_TOTAL (SM_HST + 4*WARP_STG)   // 25216

__global__ __launch_bounds__(128) void hqae_kernel(
    const float* __restrict__ x,  const float* __restrict__ qw,
    const float* __restrict__ W1, const float* __restrict__ b1,
    const float* __restrict__ W2, const float* __restrict__ b2,
    const float* __restrict__ W3, const float* __restrict__ b3,
    float* __restrict__ out, int n)
{
    __shared__ __align__(16) char sm[SM_TOTAL];
    const int tid  = threadIdx.x;
    const int lane = tid & 31, wid = tid >> 5;
    const int g = lane >> 2, t = lane & 3;

    // ---- weights into smem ----
    for (int i = tid; i < 64; i += 128) ((float*)(sm + SM_W1))[i] = W1[i];
    if (tid < 16) ((float*)(sm + SM_SB1))[tid] = b1[tid];
    if (tid < 32) ((float*)(sm + SM_SB2))[tid] = b2[tid];
    if (tid < 16) ((float*)(sm + SM_SB3))[tid] = b3[tid];
    for (int i = tid; i < 512; i += 128) {        // W2 [32][16]
        int r = i >> 4, c = i & 15;
        float hi, lo; bsplit(W2[i], hi, lo);
        *(__nv_bfloat16*)(sm + SM_W2H + r*32 + c*2) = __float2bfloat16(hi);
        *(__nv_bfloat16*)(sm + SM_W2L + r*32 + c*2) = __float2bfloat16(lo);
    }
    for (int i = tid; i < 512; i += 128) {        // W3 [16][32]
        int r = i >> 5, c = i & 31;
        float hi, lo; bsplit(W3[i], hi, lo);
        *(__nv_bfloat16*)(sm + SM_W3H + r*64 + c*2) = __float2bfloat16(hi);
        *(__nv_bfloat16*)(sm + SM_W3L + r*64 + c*2) = __float2bfloat16(lo);
    }
    if (tid == 0) {
        float c[4], s[4];
#pragma unroll
        for (int i = 0; i < 4; i++) __sincosf(qw[2*i], &s[i], &c[i]);
        float* K = (float*)(sm + SM_KC);
        K[0]=+c[0];                 K[1]=-s[0];
        K[2]=+c[0]*c[1];            K[3]=-c[0]*s[1];
        K[4]=+s[0]*c[1];            K[5]=+s[0]*s[1];
        K[6]=+c[0]*c[1]*c[2];       K[7]=-c[0]*c[1]*s[2];
        K[8]=+c[0]*s[1]*c[2];       K[9]=+c[0]*s[1]*s[2];
        K[10]=-s[0]*c[1]*c[2];      K[11]=-s[0]*c[1]*s[2];
        K[12]=-s[0]*s[1]*c[2];      K[13]=-s[0]*s[1]*s[2];
        K[14]=+c[0]*c[1]*c[2]*c[3]; K[15]=-c[0]*c[1]*c[2]*s[3];
        K[16]=+c[0]*c[1]*s[2]*c[3]; K[17]=+c[0]*c[1]*s[2]*s[3];
        K[18]=-c[0]*s[1]*c[2]*c[3]; K[19]=-c[0]*s[1]*c[2]*s[3];
        K[20]=-c[0]*s[1]*s[2]*c[3]; K[21]=-c[0]*s[1]*s[2]*s[3];
        K[22]=+s[0]*c[1]*c[2]*c[3]; K[23]=+s[0]*c[1]*c[2]*s[3];
        K[24]=-s[0]*c[1]*s[2]*c[3]; K[25]=+s[0]*c[1]*s[2]*s[3];
        K[26]=+s[0]*s[1]*c[2]*c[3]; K[27]=+s[0]*s[1]*c[2]*s[3];
        K[28]=+s[0]*s[1]*s[2]*c[3]; K[29]=+s[0]*s[1]*s[2]*s[3];
    }
    __syncthreads();

    const uint32_t su = smem_u32(sm);
    const uint32_t hiB = SM_HST + wid * WARP_STG;        // warp-private stage (hi)
    const uint32_t loB = hiB + 2560;                     // (lo)

    // ---- quantum encoder (Heisenberg 30-term, scalar fp32) ----
    const int b = blockIdx.x * 128 + tid;
    const int bs = (b < n) ? b : (n - 1);
    float z0, z1, z2, z3;
    {
        const float4* xv = (const float4*)(x + (size_t)bs * 16);
        float4 v0 = xv[0], v1 = xv[1];
        float xa[8] = {v0.x, v0.y, v0.z, v0.w, v1.x, v1.y, v1.z, v1.w};
        float bz[4], bx[4], by[4];
#pragma unroll
        for (int i = 0; i < 4; i++) {
            float sp, cz, sy_, cy_;
            __sincosf(xa[i] * PI_F, &sp, &cz);
            __sincosf(xa[i+4] * PI_F, &sy_, &cy_);
            bz[i] = cz; bx[i] = sp * cy_; by[i] = sp * sy_;
        }
        const float* K = (const float*)(sm + SM_KC);
        float a_ = bx[0]*bx[1], b_ = bx[1]*bx[2], c_ = bx[0]*bx[2];
        float d_ = by[0]*by[1], e_ = by[1]*by[2], f_ = bx[2]*bx[3];
        float h_ = bx[0]*bx[3], i_ = bz[0]*bz[2], j_ = by[2]*by[3];
        float k_ = bz[1]*bz[3], l_ = bz[0]*bx[1], m_ = by[0]*bz[1];
        float u_ = bz[0]*b_,   v_ = a_*bz[2],    w_ = m_*by[2];
        z0 = K[0]*bz[0] + K[1]*a_;
        z1 = K[2]*bz[1] + K[3]*u_ + K[4]*d_ + K[5]*c_;
        z2 = K[6]*i_ + K[7]*(bz[1]*f_) + K[8]*e_ + K[9]*(l_*bx[3])
           + K[10]*v_ + K[11]*(d_*f_) + K[12]*w_ + K[13]*h_;
        z3 = K[14]*k_ + K[15]*(i_*bx[3]) + K[16]*(bz[0]*j_) + K[17]*(bz[1]*bx[2])
           + K[18]*(u_*bz[3]) + K[19]*(e_*bx[3]) + K[20]*(by[1]*bz[2]*by[3]) + K[21]*l_
           + K[22]*(d_*bz[3]) + K[23]*(v_*bx[3]) + K[24]*(a_*j_) + K[25]*(d_*bx[2])
           + K[26]*(c_*bz[3]) + K[27]*(w_*bx[3]) + K[28]*(m_*bz[2]*by[3]) + K[29]*bx[0];
    }

    // ---- layer 1 (4->16) scalar fp32, exact; stage h1 as hi/lo bf16 rows ----
    {
        const float4* W1f = (const float4*)(sm + SM_W1);
        const float*  sb1 = (const float*)(sm + SM_SB1);
        uint32_t hp[8], lp[8];
#pragma unroll
        for (int p = 0; p < 8; p++) {
            float4 wa = W1f[2*p], wb = W1f[2*p+1];
            float ha = fmaxf(sb1[2*p]   + wa.x*z0 + wa.y*z1 + wa.z*z2 + wa.w*z3, 0.0f);
            float hb = fmaxf(sb1[2*p+1] + wb.x*z0 + wb.y*z1 + wb.z*z2 + wb.w*z3, 0.0f);
            float hia, loa, hib, lob;
            bsplit(ha, hia, loa); bsplit(hb, hib, lob);
            hp[p] = bpack(hia, hib); lp[p] = bpack(loa, lob);
        }
        char* hrow = sm + hiB + lane*80;
        char* lrow = sm + loB + lane*80;
        *(uint4*)(hrow)      = make_uint4(hp[0], hp[1], hp[2], hp[3]);
        *(uint4*)(hrow + 16) = make_uint4(hp[4], hp[5], hp[6], hp[7]);
        *(uint4*)(lrow)      = make_uint4(lp[0], lp[1], lp[2], lp[3]);
        *(uint4*)(lrow + 16) = make_uint4(lp[4], lp[5], lp[6], lp[7]);
    }
    __syncwarp();

    // ldmatrix lane-address components (canonical x4 tile order)
    const uint32_t r8    = (uint32_t)((lane & 7) + ((lane >> 3) & 1) * 8);
    const uint32_t chalf = (uint32_t)((lane >> 4) & 1) * 16;
    const float* sb2 = (const float*)(sm + SM_SB2);
    const float* sb3 = (const float*)(sm + SM_SB3);

    // ---- layer 2 (16->32) via HMMA, hi/lo compensated ----
    {
        uint32_t Ah[2][4], Al[2][4];
#pragma unroll
        for (int mt = 0; mt < 2; mt++) {
            uint32_t ra = (mt*16 + r8) * 80 + chalf;
            ldm4(Ah[mt], su + hiB + ra);
            ldm4(Al[mt], su + loB + ra);
        }
        uint32_t bh[4][2], bl[4][2];
#pragma unroll
        for (int nt = 0; nt < 4; nt++) {
            uint32_t off = (uint32_t)((8*nt + g) * 32 + 4*t);
            bh[nt][0] = *(const uint32_t*)(sm + SM_W2H + off);
            bh[nt][1] = *(const uint32_t*)(sm + SM_W2H + off + 16);
            bl[nt][0] = *(const uint32_t*)(sm + SM_W2L + off);
            bl[nt][1] = *(const uint32_t*)(sm + SM_W2L + off + 16);
        }
#pragma unroll
        for (int mt = 0; mt < 2; mt++) {
#pragma unroll
            for (int nt = 0; nt < 4; nt++) {
                float c0 = 0, c1 = 0, c2 = 0, c3 = 0;
                mma16816(c0, c1, c2, c3, Ah[mt], bh[nt][0], bh[nt][1]);
                mma16816(c0, c1, c2, c3, Al[mt], bh[nt][0], bh[nt][1]);
                mma16816(c0, c1, c2, c3, Ah[mt], bl[nt][0], bl[nt][1]);
                float bb0 = sb2[8*nt + 2*t], bb1 = sb2[8*nt + 2*t + 1];
                c0 = fmaxf(c0 + bb0, 0.0f); c1 = fmaxf(c1 + bb1, 0.0f);
                c2 = fmaxf(c2 + bb0, 0.0f); c3 = fmaxf(c3 + bb1, 0.0f);
                float h0,l0,h1,l1,h2,l2,h3,l3;
                bsplit(c0,h0,l0); bsplit(c1,h1,l1); bsplit(c2,h2,l2); bsplit(c3,h3,l3);
                uint32_t co = (uint32_t)(16*nt + 4*t);
                uint32_t rA = (uint32_t)(mt*16 + g) * 80;
                uint32_t rB = (uint32_t)(mt*16 + g + 8) * 80;
                *(uint32_t*)(sm + hiB + rA + co) = bpack(h0, h1);
                *(uint32_t*)(sm + hiB + rB + co) = bpack(h2, h3);
                *(uint32_t*)(sm + loB + rA + co) = bpack(l0, l1);
                *(uint32_t*)(sm + loB + rB + co) = bpack(l2, l3);
            }
        }
    }
    __syncwarp();

    // ---- layer 3 (32->16) via HMMA, direct gmem epilogue ----
    {
        uint32_t bh[2][2][2], bl[2][2][2];
#pragma unroll
        for (int nt = 0; nt < 2; nt++)
#pragma unroll
            for (int ks = 0; ks < 2; ks++) {
                uint32_t off = (uint32_t)((8*nt + g) * 64 + 4*t + 32*ks);
                bh[nt][ks][0] = *(const uint32_t*)(sm + SM_W3H + off);
                bh[nt][ks][1] = *(const uint32_t*)(sm + SM_W3H + off + 16);
                bl[nt][ks][0] = *(const uint32_t*)(sm + SM_W3L + off);
                bl[nt][ks][1] = *(const uint32_t*)(sm + SM_W3L + off + 16);
            }
        const int ebase = blockIdx.x * 128 + wid * 32;
#pragma unroll
        for (int mt = 0; mt < 2; mt++) {
            uint32_t Ah[2][4], Al[2][4];
#pragma unroll
            for (int ks = 0; ks < 2; ks++) {
                uint32_t ra = (uint32_t)(mt*16 + r8) * 80 + chalf + 32*ks;
                ldm4(Ah[ks], su + hiB + ra);
                ldm4(Al[ks], su + loB + ra);
            }
#pragma unroll
            for (int nt = 0; nt < 2; nt++) {
                float c0 = 0, c1 = 0, c2 = 0, c3 = 0;
#pragma unroll
                for (int ks = 0; ks < 2; ks++) {
                    mma16816(c0, c1, c2, c3, Ah[ks], bh[nt][ks][0], bh[nt][ks][1]);
                    mma16816(c0, c1, c2, c3, Al[ks], bh[nt][ks][0], bh[nt][ks][1]);
                    mma16816(c0, c1, c2, c3, Ah[ks], bl[nt][ks][0], bl[nt][ks][1]);
                }
                float bb0 = sb3[8*nt + 2*t], bb1 = sb3[8*nt + 2*t + 1];
                int e0 = ebase + mt*16 + g, e1 = e0 + 8;
                if (e0 < n) *(float2*)(out + (size_t)e0*16 + 8*nt + 2*t) = make_float2(c0 + bb0, c1 + bb1);
                if (e1 < n) *(float2*)(out + (size_t)e1*16 + 8*nt + 2*t) = make_float2(c2 + bb0, c3 + bb1);
            }
        }
    }
}

extern "C" void kernel_launch(void* const* d_in, const int* in_sizes, int n_in,
                              void* d_out, int out_size)
{
    const float* x  = (const float*)d_in[0];
    const float* qw = (const float*)d_in[1];
    const float* W1 = (const float*)d_in[2];
    const float* b1 = (const float*)d_in[3];
    const float* W2 = (const float*)d_in[4];
    const float* b2 = (const float*)d_in[5];
    const float* W3 = (const float*)d_in[6];
    const float* b3 = (const float*)d_in[7];
    float* out = (float*)d_out;

    const int n = in_sizes[0] / 16;
    const int blocks = (n + 127) / 128;
    hqae_kernel<<<blocks, 128>>>(x, qw, W1, b1, W2, b2, W3, b3, out, n);
}